// round 3
// baseline (speedup 1.0000x reference)
#include <cuda_runtime.h>
#include <math.h>

#define RR 64
#define DT_C 0.1f
#define TAU_MIN_C 0.1f
#define TAU_MAX_C 10.0f
#define SCALING_C 2.0f          // 128/64

#define MAX_M 16384
#define MAX_O 4096

// scratch (device globals: no allocation allowed)
__device__ float g_hidden[MAX_O * RR];     // 1 MB
__device__ float g_t[MAX_M * RR];          // 4 MB

// ---------------------------------------------------------------------------
// Kernel 1: liquid dynamics. hidden starts at hidden_B (zeros), target=lora_B.
// Per row o (64 threads, thread r owns feature r):
//   f   = sigmoid([target,h] @ Wg[r] + bg[r])
//   tau = 0.1 + 9.9*sigmoid([target,h] @ Wt[r] + bt[r])
//   a = 1/tau + f ; decay = exp(-a*dt)
//   h = h*decay + (f/a)*target*(1-decay)       (3 steps)
// W stored transposed in smem: WT[k*132 + c], c<64 -> gate col, c>=64 -> tau.
// Reads at fixed k across threads are consecutive -> conflict-free; inp[k]
// is a broadcast. Target-half of both dots is precomputed once per row.
// ---------------------------------------------------------------------------
__global__ __launch_bounds__(256) void liquid_kernel(
    const float* __restrict__ lora_B,
    const float* __restrict__ hidden0,
    const float* __restrict__ W_gate, const float* __restrict__ b_gate,
    const float* __restrict__ W_tau,  const float* __restrict__ b_tau,
    int O)
{
    extern __shared__ float WT[];            // 128 * 132 floats
    __shared__ float inp_s[4][64];

    int t = threadIdx.x;

    // transpose-load both weight matrices [64][128] -> WT[k][c]
    for (int idx = t; idx < 64 * 128; idx += 256) {
        int r = idx >> 7;
        int k = idx & 127;
        WT[k * 132 + r]      = W_gate[idx];
        WT[k * 132 + 64 + r] = W_tau[idx];
    }
    __syncthreads();

    int g = t >> 6;                          // group 0..3
    int r = t & 63;
    int group_id = blockIdx.x * 4 + g;
    int n_groups = gridDim.x * 4;

    float bg = b_gate[r];
    float bt = b_tau[r];

    for (int o = group_id; o < O; o += n_groups) {
        float target = lora_B[o * RR + r];

        // target-half partial dots (columns k = 0..63 of W)
        inp_s[g][r] = target;
        __syncthreads();
        float pg = bg, pt = bt;
        #pragma unroll 16
        for (int k = 0; k < 64; k++) {
            float v = inp_s[g][k];
            pg += v * WT[k * 132 + r];
            pt += v * WT[k * 132 + 64 + r];
        }
        __syncthreads();

        float h = hidden0[o * RR + r];

        #pragma unroll
        for (int step = 0; step < 3; step++) {
            inp_s[g][r] = h;
            __syncthreads();
            float ga = pg, ta = pt;
            #pragma unroll 16
            for (int k = 0; k < 64; k++) {
                float v = inp_s[g][k];
                ga += v * WT[(64 + k) * 132 + r];
                ta += v * WT[(64 + k) * 132 + 64 + r];
            }
            __syncthreads();
            float f    = 1.0f / (1.0f + expf(-ga));
            float tau  = TAU_MIN_C + (TAU_MAX_C - TAU_MIN_C) / (1.0f + expf(-ta));
            float a    = 1.0f / tau + f;
            float dec  = expf(-a * DT_C);
            h = h * dec + (f / a) * target * (1.0f - dec);
        }
        g_hidden[o * RR + r] = h;
    }
}

// ---------------------------------------------------------------------------
// Kernel 2: t[m][r] = sum_d x[m][d] * A[r][d]    (M x 64, K = D)
// Block tile 64(M) x 64(R=all), BK=32, 256 threads, 4x4 per thread.
// Xs/As stored [row][k] with pad 33 (conflict-free b-reads: tx stride 1).
// ---------------------------------------------------------------------------
__global__ __launch_bounds__(256, 2) void gemm1_kernel(
    const float* __restrict__ x, const float* __restrict__ A,
    int M, int D)
{
    __shared__ float Xs[64 * 33];
    __shared__ float As[64 * 33];

    int t  = threadIdx.x;
    int tx = t & 15;
    int ty = t >> 4;
    int m0 = blockIdx.x * 64;

    int rowL = t >> 2;              // 0..63
    int colL = (t & 3) * 8;         // 0,8,16,24

    float acc[4][4];
    #pragma unroll
    for (int i = 0; i < 4; i++)
        #pragma unroll
        for (int j = 0; j < 4; j++) acc[i][j] = 0.0f;

    const float* xg = x + (m0 + rowL) * D + colL;
    const float* ag = A + rowL * D + colL;

    for (int kt = 0; kt < D; kt += 32) {
        float4 xv0 = *(const float4*)(xg + kt);
        float4 xv1 = *(const float4*)(xg + kt + 4);
        float4 av0 = *(const float4*)(ag + kt);
        float4 av1 = *(const float4*)(ag + kt + 4);
        __syncthreads();            // previous iteration's reads done
        float* xd = &Xs[rowL * 33 + colL];
        xd[0] = xv0.x; xd[1] = xv0.y; xd[2] = xv0.z; xd[3] = xv0.w;
        xd[4] = xv1.x; xd[5] = xv1.y; xd[6] = xv1.z; xd[7] = xv1.w;
        float* ad = &As[rowL * 33 + colL];
        ad[0] = av0.x; ad[1] = av0.y; ad[2] = av0.z; ad[3] = av0.w;
        ad[4] = av1.x; ad[5] = av1.y; ad[6] = av1.z; ad[7] = av1.w;
        __syncthreads();

        #pragma unroll
        for (int k = 0; k < 32; k++) {
            float a0 = Xs[(ty     ) * 33 + k];
            float a1 = Xs[(ty + 16) * 33 + k];
            float a2 = Xs[(ty + 32) * 33 + k];
            float a3 = Xs[(ty + 48) * 33 + k];
            float b0 = As[(tx     ) * 33 + k];
            float b1 = As[(tx + 16) * 33 + k];
            float b2 = As[(tx + 32) * 33 + k];
            float b3 = As[(tx + 48) * 33 + k];
            acc[0][0] += a0 * b0; acc[0][1] += a0 * b1; acc[0][2] += a0 * b2; acc[0][3] += a0 * b3;
            acc[1][0] += a1 * b0; acc[1][1] += a1 * b1; acc[1][2] += a1 * b2; acc[1][3] += a1 * b3;
            acc[2][0] += a2 * b0; acc[2][1] += a2 * b1; acc[2][2] += a2 * b2; acc[2][3] += a2 * b3;
            acc[3][0] += a3 * b0; acc[3][1] += a3 * b1; acc[3][2] += a3 * b2; acc[3][3] += a3 * b3;
        }
    }

    #pragma unroll
    for (int i = 0; i < 4; i++) {
        int m = m0 + ty + 16 * i;
        #pragma unroll
        for (int j = 0; j < 4; j++) {
            g_t[m * RR + tx + 16 * j] = acc[i][j];
        }
    }
}

// ---------------------------------------------------------------------------
// Kernel 3: out[m][o] = SCALING * sum_r t[m][r] * hidden[o][r]   (K = 64)
// Block tile 64 x 64, single K pass, 256 threads, 4x4 per thread, pad 65.
// ---------------------------------------------------------------------------
__global__ __launch_bounds__(256, 2) void gemm2_kernel(
    float* __restrict__ out, int M, int O)
{
    __shared__ float Ts[64 * 65];
    __shared__ float Bs[64 * 65];

    int t  = threadIdx.x;
    int tx = t & 15;
    int ty = t >> 4;
    int m0 = blockIdx.x * 64;
    int o0 = blockIdx.y * 64;

    int rowL = t >> 2;              // 0..63
    int colL = (t & 3) * 16;        // 0,16,32,48

    const float* tg = g_t      + (m0 + rowL) * RR + colL;
    const float* bg = g_hidden + (o0 + rowL) * RR + colL;
    #pragma unroll
    for (int j = 0; j < 16; j += 4) {
        float4 v = *(const float4*)(tg + j);
        float4 w = *(const float4*)(bg + j);
        float* td = &Ts[rowL * 65 + colL + j];
        td[0] = v.x; td[1] = v.y; td[2] = v.z; td[3] = v.w;
        float* bd = &Bs[rowL * 65 + colL + j];
        bd[0] = w.x; bd[1] = w.y; bd[2] = w.z; bd[3] = w.w;
    }
    __syncthreads();

    float acc[4][4];
    #pragma unroll
    for (int i = 0; i < 4; i++)
        #pragma unroll
        for (int j = 0; j < 4; j++) acc[i][j] = 0.0f;

    #pragma unroll 16
    for (int k = 0; k < 64; k++) {
        float a0 = Ts[(ty     ) * 65 + k];
        float a1 = Ts[(ty + 16) * 65 + k];
        float a2 = Ts[(ty + 32) * 65 + k];
        float a3 = Ts[(ty + 48) * 65 + k];
        float b0 = Bs[(tx     ) * 65 + k];
        float b1 = Bs[(tx + 16) * 65 + k];
        float b2 = Bs[(tx + 32) * 65 + k];
        float b3 = Bs[(tx + 48) * 65 + k];
        acc[0][0] += a0 * b0; acc[0][1] += a0 * b1; acc[0][2] += a0 * b2; acc[0][3] += a0 * b3;
        acc[1][0] += a1 * b0; acc[1][1] += a1 * b1; acc[1][2] += a1 * b2; acc[1][3] += a1 * b3;
        acc[2][0] += a2 * b0; acc[2][1] += a2 * b1; acc[2][2] += a2 * b2; acc[2][3] += a2 * b3;
        acc[3][0] += a3 * b0; acc[3][1] += a3 * b1; acc[3][2] += a3 * b2; acc[3][3] += a3 * b3;
    }

    #pragma unroll
    for (int i = 0; i < 4; i++) {
        int m = m0 + ty + 16 * i;
        #pragma unroll
        for (int j = 0; j < 4; j++) {
            out[m * O + o0 + tx + 16 * j] = SCALING_C * acc[i][j];
        }
    }
}

// ---------------------------------------------------------------------------
extern "C" void kernel_launch(void* const* d_in, const int* in_sizes, int n_in,
                              void* d_out, int out_size)
{
    const float* x       = (const float*)d_in[0];
    const float* lora_A  = (const float*)d_in[1];
    const float* lora_B  = (const float*)d_in[2];
    const float* hidden0 = (const float*)d_in[3];
    const float* W_gate  = (const float*)d_in[4];
    const float* b_gate  = (const float*)d_in[5];
    const float* W_tau   = (const float*)d_in[6];
    const float* b_tau   = (const float*)d_in[7];
    float* out = (float*)d_out;

    int R = in_sizes[5];                 // 64
    int D = in_sizes[1] / R;             // 4096
    int O = in_sizes[2] / R;             // 4096
    int M = in_sizes[0] / D;             // 16384

    // liquid: dynamic smem 128*132 floats = 67584 B (> default 48KB)
    static int smem_set = 0;
    (void)smem_set;
    cudaFuncSetAttribute(liquid_kernel,
                         cudaFuncAttributeMaxDynamicSharedMemorySize,
                         128 * 132 * (int)sizeof(float));

    liquid_kernel<<<128, 256, 128 * 132 * sizeof(float)>>>(
        lora_B, hidden0, W_gate, b_gate, W_tau, b_tau, O);

    gemm1_kernel<<<M / 64, 256>>>(x, lora_A, M, D);

    dim3 g2(M / 64, O / 64);
    gemm2_kernel<<<g2, 256>>>(out, M, O);
}

// round 6
// speedup vs baseline: 1.5989x; 1.5989x over previous
#include <cuda_runtime.h>
#include <cuda_bf16.h>
#include <math.h>
#include <stdint.h>

#define RR 64
#define DT_C 0.1f
#define TAU_MIN_C 0.1f
#define TAU_MAX_C 10.0f
#define SCALING_C 2.0f          // 128/64

#define MAX_M 16384
#define MAX_O 4096

// scratch (device globals: no allocation allowed)
__device__ __align__(16) __nv_bfloat16 g_t_hi[MAX_M * RR];   // 2 MB
__device__ __align__(16) __nv_bfloat16 g_t_lo[MAX_M * RR];   // 2 MB
__device__ __align__(16) __nv_bfloat16 g_hB_hi[MAX_O * RR];  // split of 2*hidden
__device__ __align__(16) __nv_bfloat16 g_hB_lo[MAX_O * RR];

// ---------------------------------------------------------------------------
// helpers
// ---------------------------------------------------------------------------
__device__ __forceinline__ uint32_t smem_u32(const void* p) {
    uint32_t a;
    asm("{ .reg .u64 t; cvta.to.shared.u64 t, %1; cvt.u32.u64 %0, t; }"
        : "=r"(a) : "l"(p));
    return a;
}
__device__ __forceinline__ uint32_t sw128(uint32_t o) { return o ^ ((o >> 3) & 0x70); }

__device__ __forceinline__ void sts128(uint32_t a, uint32_t x, uint32_t y,
                                       uint32_t z, uint32_t w) {
    asm volatile("st.shared.v4.b32 [%0], {%1,%2,%3,%4};"
                 :: "r"(a), "r"(x), "r"(y), "r"(z), "r"(w) : "memory");
}
__device__ __forceinline__ void ldm_x4(uint32_t* r, uint32_t addr) {
    asm volatile("ldmatrix.sync.aligned.m8n8.x4.shared.b16 {%0,%1,%2,%3}, [%4];"
                 : "=r"(r[0]), "=r"(r[1]), "=r"(r[2]), "=r"(r[3]) : "r"(addr));
}
// D += A * B, bf16 inputs, fp32 accum (register-path tensor core, sm_80+)
__device__ __forceinline__ void mma16816(float* d, const uint32_t* a, const uint32_t* b) {
    asm volatile(
        "mma.sync.aligned.m16n8k16.row.col.f32.bf16.bf16.f32 "
        "{%0,%1,%2,%3}, {%4,%5,%6,%7}, {%8,%9}, {%0,%1,%2,%3};"
        : "+f"(d[0]), "+f"(d[1]), "+f"(d[2]), "+f"(d[3])
        : "r"(a[0]), "r"(a[1]), "r"(a[2]), "r"(a[3]), "r"(b[0]), "r"(b[1]));
}
// split a pair of fp32 into hi/lo bf16x2 (packed, element order preserved)
__device__ __forceinline__ void split2(float a, float b, uint32_t& hi, uint32_t& lo) {
    __nv_bfloat162 h = __floats2bfloat162_rn(a, b);
    float2 hf = __bfloat1622float2(h);
    __nv_bfloat162 l = __floats2bfloat162_rn(a - hf.x, b - hf.y);
    hi = *reinterpret_cast<uint32_t*>(&h);
    lo = *reinterpret_cast<uint32_t*>(&l);
}

// ---------------------------------------------------------------------------
// Kernel 1: liquid dynamics. One row per 64-thread group, 4 groups per block.
// Writes B_eff = 2*hidden_new pre-split into bf16 hi/lo (SCALING folded here).
// ---------------------------------------------------------------------------
__global__ __launch_bounds__(256) void liquid_kernel(
    const float* __restrict__ lora_B,
    const float* __restrict__ hidden0,
    const float* __restrict__ W_gate, const float* __restrict__ b_gate,
    const float* __restrict__ W_tau,  const float* __restrict__ b_tau,
    int O)
{
    extern __shared__ float WT[];            // 128 * 132 floats
    __shared__ float inp_s[4][64];

    int t = threadIdx.x;
    for (int idx = t; idx < 64 * 128; idx += 256) {
        int r = idx >> 7;
        int k = idx & 127;
        WT[k * 132 + r]      = W_gate[idx];
        WT[k * 132 + 64 + r] = W_tau[idx];
    }
    __syncthreads();

    int g = t >> 6;
    int r = t & 63;
    int o = blockIdx.x * 4 + g;
    if (o >= O) return;

    float bg = b_gate[r];
    float bt = b_tau[r];
    float target = lora_B[o * RR + r];

    inp_s[g][r] = target;
    __syncthreads();
    float pg = bg, pt = bt;
    #pragma unroll 16
    for (int k = 0; k < 64; k++) {
        float v = inp_s[g][k];
        pg += v * WT[k * 132 + r];
        pt += v * WT[k * 132 + 64 + r];
    }
    __syncthreads();

    float h = hidden0[o * RR + r];
    #pragma unroll
    for (int step = 0; step < 3; step++) {
        inp_s[g][r] = h;
        __syncthreads();
        float ga = pg, ta = pt;
        #pragma unroll 16
        for (int k = 0; k < 64; k++) {
            float v = inp_s[g][k];
            ga += v * WT[(64 + k) * 132 + r];
            ta += v * WT[(64 + k) * 132 + 64 + r];
        }
        __syncthreads();
        float f    = 1.0f / (1.0f + expf(-ga));
        float tau  = TAU_MIN_C + (TAU_MAX_C - TAU_MIN_C) / (1.0f + expf(-ta));
        float a    = 1.0f / tau + f;
        float dec  = expf(-a * DT_C);
        h = h * dec + (f / a) * target * (1.0f - dec);
    }

    float v = SCALING_C * h;
    __nv_bfloat16 hb = __float2bfloat16_rn(v);
    float lo = v - __bfloat162float(hb);
    g_hB_hi[o * RR + r] = hb;
    g_hB_lo[o * RR + r] = __float2bfloat16_rn(lo);
}

// ---------------------------------------------------------------------------
// Kernel 2: t = x @ A^T via mma.sync bf16 split (hi*hi + hi*lo + lo*hi).
// CTA tile 128(M) x 64(N=R), K-tiles of 64. 8 warps as 4(m) x 2(n),
// warp tile 32x32. Register-prefetch overlaps global loads with MMA.
// Epilogue writes t pre-split to bf16 hi/lo.
// ---------------------------------------------------------------------------
__global__ __launch_bounds__(256) void gemm1_mma(
    const float* __restrict__ x, const float* __restrict__ A, int M, int D)
{
    extern __shared__ char dsm[];
    uint32_t sb  = (smem_u32(dsm) + 1023) & ~1023u;
    uint32_t xhi = sb;                 // 128 rows * 128B
    uint32_t xlo = sb + 16384;
    uint32_t ahi = sb + 32768;         // 64 rows * 128B
    uint32_t alo = sb + 40960;

    int tid = threadIdx.x, wid = tid >> 5, lane = tid & 31;
    int warp_m = wid >> 1, warp_n = wid & 1;
    int tt = lane >> 3, rr = lane & 7;
    int g  = lane >> 2, tq = lane & 3;

    int m0 = blockIdx.x * 128;

    // staging: x rows 0..127 (2 thr/row, 32 floats each); A rows 0..63 (4 thr/row)
    int xrow = tid >> 1, xcb = (tid & 1) * 32;
    int arow = tid >> 2, acb = (tid & 3) * 16;
    const float* xg = x + (size_t)(m0 + xrow) * D + xcb;
    const float* ag = A + (size_t)arow * D + acb;

    // ldmatrix lane geometry
    int a_row  = warp_m * 32 + (tt & 1) * 8 + rr;   // + mt*16
    int a_colb = (tt >> 1) * 16;                    // + kk*32
    int b_row  = warp_n * 32 + (tt >> 1) * 8 + rr;  // + np*16
    int b_colb = (tt & 1) * 16;                     // + kk*32

    float acc[2][4][4];
    #pragma unroll
    for (int i = 0; i < 2; i++)
        #pragma unroll
        for (int j = 0; j < 4; j++)
            #pragma unroll
            for (int k = 0; k < 4; k++) acc[i][j][k] = 0.0f;

    float4 xv[8], av[4];
    #pragma unroll
    for (int j = 0; j < 8; j++) xv[j] = ((const float4*)xg)[j];
    #pragma unroll
    for (int j = 0; j < 4; j++) av[j] = ((const float4*)ag)[j];

    int nkt = D >> 6;
    for (int kt = 0; kt < nkt; kt++) {
        __syncthreads();   // prior compute done reading smem
        #pragma unroll
        for (int j = 0; j < 4; j++) {
            uint32_t h0, l0, h1, l1, h2, l2, h3, l3;
            split2(xv[2*j].x,   xv[2*j].y,   h0, l0);
            split2(xv[2*j].z,   xv[2*j].w,   h1, l1);
            split2(xv[2*j+1].x, xv[2*j+1].y, h2, l2);
            split2(xv[2*j+1].z, xv[2*j+1].w, h3, l3);
            uint32_t off = sw128((uint32_t)(xrow * 128 + xcb * 2 + j * 16));
            sts128(xhi + off, h0, h1, h2, h3);
            sts128(xlo + off, l0, l1, l2, l3);
        }
        #pragma unroll
        for (int j = 0; j < 2; j++) {
            uint32_t h0, l0, h1, l1, h2, l2, h3, l3;
            split2(av[2*j].x,   av[2*j].y,   h0, l0);
            split2(av[2*j].z,   av[2*j].w,   h1, l1);
            split2(av[2*j+1].x, av[2*j+1].y, h2, l2);
            split2(av[2*j+1].z, av[2*j+1].w, h3, l3);
            uint32_t off = sw128((uint32_t)(arow * 128 + acb * 2 + j * 16));
            sts128(ahi + off, h0, h1, h2, h3);
            sts128(alo + off, l0, l1, l2, l3);
        }
        __syncthreads();

        if (kt + 1 < nkt) {     // prefetch next tile; latency hidden by MMAs below
            const float4* xp = (const float4*)(xg + (size_t)(kt + 1) * 64);
            #pragma unroll
            for (int j = 0; j < 8; j++) xv[j] = xp[j];
            const float4* ap = (const float4*)(ag + (size_t)(kt + 1) * 64);
            #pragma unroll
            for (int j = 0; j < 4; j++) av[j] = ap[j];
        }

        #pragma unroll
        for (int kk = 0; kk < 4; kk++) {
            uint32_t axh[2][4], axl[2][4];
            #pragma unroll
            for (int mt = 0; mt < 2; mt++) {
                uint32_t off = sw128((uint32_t)((a_row + mt * 16) * 128 + a_colb + kk * 32));
                ldm_x4(axh[mt], xhi + off);
                ldm_x4(axl[mt], xlo + off);
            }
            uint32_t bh[4][2], bl[4][2];
            #pragma unroll
            for (int np = 0; np < 2; np++) {
                uint32_t off = sw128((uint32_t)((b_row + np * 16) * 128 + b_colb + kk * 32));
                uint32_t r4[4];
                ldm_x4(r4, ahi + off);
                bh[2*np][0] = r4[0]; bh[2*np][1] = r4[1];
                bh[2*np+1][0] = r4[2]; bh[2*np+1][1] = r4[3];
                ldm_x4(r4, alo + off);
                bl[2*np][0] = r4[0]; bl[2*np][1] = r4[1];
                bl[2*np+1][0] = r4[2]; bl[2*np+1][1] = r4[3];
            }
            #pragma unroll
            for (int mt = 0; mt < 2; mt++)
                #pragma unroll
                for (int nt = 0; nt < 4; nt++) {
                    mma16816(acc[mt][nt], axh[mt], bh[nt]);
                    mma16816(acc[mt][nt], axh[mt], bl[nt]);
                    mma16816(acc[mt][nt], axl[mt], bh[nt]);
                }
        }
    }

    // epilogue: split t into bf16 hi/lo
    #pragma unroll
    for (int mt = 0; mt < 2; mt++) {
        int m = m0 + warp_m * 32 + mt * 16 + g;
        #pragma unroll
        for (int nt = 0; nt < 4; nt++) {
            int n = warp_n * 32 + nt * 8 + 2 * tq;
            uint32_t hi, lo;
            split2(acc[mt][nt][0], acc[mt][nt][1], hi, lo);
            *(uint32_t*)(g_t_hi + (size_t)m * RR + n) = hi;
            *(uint32_t*)(g_t_lo + (size_t)m * RR + n) = lo;
            split2(acc[mt][nt][2], acc[mt][nt][3], hi, lo);
            *(uint32_t*)(g_t_hi + (size_t)(m + 8) * RR + n) = hi;
            *(uint32_t*)(g_t_lo + (size_t)(m + 8) * RR + n) = lo;
        }
    }
}

// ---------------------------------------------------------------------------
// Kernel 3: out = t @ Beff^T (SCALING folded into Beff), K = 64 single shot.
// CTA tile 128(M) x 64(O); operands already bf16 split (L2-resident).
// ---------------------------------------------------------------------------
__global__ __launch_bounds__(256) void gemm2_mma(
    float* __restrict__ out, int M, int O)
{
    extern __shared__ char dsm[];
    uint32_t sb  = (smem_u32(dsm) + 1023) & ~1023u;
    uint32_t thi = sb;                 // 128 rows * 128B
    uint32_t tlo = sb + 16384;
    uint32_t hhi = sb + 32768;         // 64 rows * 128B
    uint32_t hlo = sb + 40960;

    int tid = threadIdx.x, wid = tid >> 5, lane = tid & 31;
    int warp_m = wid >> 1, warp_n = wid & 1;
    int tt = lane >> 3, rr = lane & 7;
    int g  = lane >> 2, tq = lane & 3;

    int m0 = blockIdx.x * 128;
    int o0 = blockIdx.y * 64;

    // t tiles: 128 rows x 8 x16B chunks per array -> 4 chunks/thread/array
    #pragma unroll
    for (int j = 0; j < 4; j++) {
        int i = tid + 256 * j;
        int row = i >> 3, c = i & 7;
        uint4 vh = ((const uint4*)(g_t_hi + (size_t)(m0 + row) * RR))[c];
        uint4 vl = ((const uint4*)(g_t_lo + (size_t)(m0 + row) * RR))[c];
        uint32_t off = sw128((uint32_t)(row * 128 + c * 16));
        sts128(thi + off, vh.x, vh.y, vh.z, vh.w);
        sts128(tlo + off, vl.x, vl.y, vl.z, vl.w);
    }
    // h tiles: 64 rows x 8 chunks -> 2 chunks/thread/array
    #pragma unroll
    for (int j = 0; j < 2; j++) {
        int i = tid + 256 * j;
        int row = i >> 3, c = i & 7;
        uint4 vh = ((const uint4*)(g_hB_hi + (size_t)(o0 + row) * RR))[c];
        uint4 vl = ((const uint4*)(g_hB_lo + (size_t)(o0 + row) * RR))[c];
        uint32_t off = sw128((uint32_t)(row * 128 + c * 16));
        sts128(hhi + off, vh.x, vh.y, vh.z, vh.w);
        sts128(hlo + off, vl.x, vl.y, vl.z, vl.w);
    }
    __syncthreads();

    int a_row  = warp_m * 32 + (tt & 1) * 8 + rr;
    int a_colb = (tt >> 1) * 16;
    int b_row  = warp_n * 32 + (tt >> 1) * 8 + rr;
    int b_colb = (tt & 1) * 16;

    float acc[2][4][4];
    #pragma unroll
    for (int i = 0; i < 2; i++)
        #pragma unroll
        for (int j = 0; j < 4; j++)
            #pragma unroll
            for (int k = 0; k < 4; k++) acc[i][j][k] = 0.0f;

    #pragma unroll
    for (int kk = 0; kk < 4; kk++) {
        uint32_t axh[2][4], axl[2][4];
        #pragma unroll
        for (int mt = 0; mt < 2; mt++) {
            uint32_t off = sw128((uint32_t)((a_row + mt * 16) * 128 + a_colb + kk * 32));
            ldm_x4(axh[mt], thi + off);
            ldm_x4(axl[mt], tlo + off);
        }
        uint32_t bh[4][2], bl[4][2];
        #pragma unroll
        for (int np = 0; np < 2; np++) {
            uint32_t off = sw128((uint32_t)((b_row + np * 16) * 128 + b_colb + kk * 32));
            uint32_t r4[4];
            ldm_x4(r4, hhi + off);
            bh[2*np][0] = r4[0]; bh[2*np][1] = r4[1];
            bh[2*np+1][0] = r4[2]; bh[2*np+1][1] = r4[3];
            ldm_x4(r4, hlo + off);
            bl[2*np][0] = r4[0]; bl[2*np][1] = r4[1];
            bl[2*np+1][0] = r4[2]; bl[2*np+1][1] = r4[3];
        }
        #pragma unroll
        for (int mt = 0; mt < 2; mt++)
            #pragma unroll
            for (int nt = 0; nt < 4; nt++) {
                mma16816(acc[mt][nt], axh[mt], bh[nt]);
                mma16816(acc[mt][nt], axh[mt], bl[nt]);
                mma16816(acc[mt][nt], axl[mt], bh[nt]);
            }
    }

    #pragma unroll
    for (int mt = 0; mt < 2; mt++) {
        int m = m0 + warp_m * 32 + mt * 16 + g;
        #pragma unroll
        for (int nt = 0; nt < 4; nt++) {
            int o = o0 + warp_n * 32 + nt * 8 + 2 * tq;
            float2 v0 = make_float2(acc[mt][nt][0], acc[mt][nt][1]);
            *(float2*)(out + (size_t)m * O + o) = v0;
            float2 v1 = make_float2(acc[mt][nt][2], acc[mt][nt][3]);
            *(float2*)(out + (size_t)(m + 8) * O + o) = v1;
        }
    }
}

// ---------------------------------------------------------------------------
extern "C" void kernel_launch(void* const* d_in, const int* in_sizes, int n_in,
                              void* d_out, int out_size)
{
    const float* x       = (const float*)d_in[0];
    const float* lora_A  = (const float*)d_in[1];
    const float* lora_B  = (const float*)d_in[2];
    const float* hidden0 = (const float*)d_in[3];
    const float* W_gate  = (const float*)d_in[4];
    const float* b_gate  = (const float*)d_in[5];
    const float* W_tau   = (const float*)d_in[6];
    const float* b_tau   = (const float*)d_in[7];
    float* out = (float*)d_out;

    int R = in_sizes[5];                 // 64
    int D = in_sizes[1] / R;             // 4096
    int O = in_sizes[2] / R;             // 4096
    int M = in_sizes[0] / D;             // 16384

    cudaFuncSetAttribute(liquid_kernel,
                         cudaFuncAttributeMaxDynamicSharedMemorySize,
                         128 * 132 * (int)sizeof(float));
    cudaFuncSetAttribute(gemm1_mma,
                         cudaFuncAttributeMaxDynamicSharedMemorySize, 50176);
    cudaFuncSetAttribute(gemm2_mma,
                         cudaFuncAttributeMaxDynamicSharedMemorySize, 50176);

    liquid_kernel<<<(O + 3) / 4, 256, 128 * 132 * sizeof(float)>>>(
        lora_B, hidden0, W_gate, b_gate, W_tau, b_tau, O);

    gemm1_mma<<<M / 128, 256, 50176>>>(x, lora_A, M, D);

    dim3 g2(M / 128, O / 64);
    gemm2_mma<<<g2, 256, 50176>>>(out, M, O);
}

// round 7
// speedup vs baseline: 2.6241x; 1.6412x over previous
#include <cuda_runtime.h>
#include <cuda_bf16.h>
#include <math.h>
#include <stdint.h>

#define RR 64
#define DT_C 0.1f
#define TAU_MIN_C 0.1f
#define TAU_MAX_C 10.0f
#define SCALING_C 2.0f          // 128/64

#define MAX_M 16384
#define MAX_O 4096

// scratch (device globals: no allocation allowed)
__device__ __align__(16) __nv_bfloat16 g_t_hi[MAX_M * RR];   // 2 MB
__device__ __align__(16) __nv_bfloat16 g_t_lo[MAX_M * RR];   // 2 MB
__device__ __align__(16) __nv_bfloat16 g_hB_hi[MAX_O * RR];  // split of 2*hidden
__device__ __align__(16) __nv_bfloat16 g_hB_lo[MAX_O * RR];

// ---------------------------------------------------------------------------
// helpers
// ---------------------------------------------------------------------------
__device__ __forceinline__ uint32_t smem_u32(const void* p) {
    uint32_t a;
    asm("{ .reg .u64 t; cvta.to.shared.u64 t, %1; cvt.u32.u64 %0, t; }"
        : "=r"(a) : "l"(p));
    return a;
}
__device__ __forceinline__ uint32_t sw128(uint32_t o) { return o ^ ((o >> 3) & 0x70); }

__device__ __forceinline__ void sts128(uint32_t a, uint32_t x, uint32_t y,
                                       uint32_t z, uint32_t w) {
    asm volatile("st.shared.v4.b32 [%0], {%1,%2,%3,%4};"
                 :: "r"(a), "r"(x), "r"(y), "r"(z), "r"(w) : "memory");
}
__device__ __forceinline__ void ldm_x4(uint32_t* r, uint32_t addr) {
    asm volatile("ldmatrix.sync.aligned.m8n8.x4.shared.b16 {%0,%1,%2,%3}, [%4];"
                 : "=r"(r[0]), "=r"(r[1]), "=r"(r[2]), "=r"(r[3]) : "r"(addr));
}
// D += A * B, bf16 inputs, fp32 accum (register-path tensor core, sm_80+)
__device__ __forceinline__ void mma16816(float* d, const uint32_t* a, const uint32_t* b) {
    asm volatile(
        "mma.sync.aligned.m16n8k16.row.col.f32.bf16.bf16.f32 "
        "{%0,%1,%2,%3}, {%4,%5,%6,%7}, {%8,%9}, {%0,%1,%2,%3};"
        : "+f"(d[0]), "+f"(d[1]), "+f"(d[2]), "+f"(d[3])
        : "r"(a[0]), "r"(a[1]), "r"(a[2]), "r"(a[3]), "r"(b[0]), "r"(b[1]));
}
// split a pair of fp32 into hi/lo bf16x2 (packed, element order preserved)
__device__ __forceinline__ void split2(float a, float b, uint32_t& hi, uint32_t& lo) {
    __nv_bfloat162 h = __floats2bfloat162_rn(a, b);
    float2 hf = __bfloat1622float2(h);
    __nv_bfloat162 l = __floats2bfloat162_rn(a - hf.x, b - hf.y);
    hi = *reinterpret_cast<uint32_t*>(&h);
    lo = *reinterpret_cast<uint32_t*>(&l);
}

// ---------------------------------------------------------------------------
// Kernel 1: liquid dynamics, 4 rows per thread (shared WT loads, 8 indep
// FMA chains). 4 groups of 64 threads; each group processes 4 rows/pass.
// Writes B_eff = 2*hidden_new pre-split into bf16 hi/lo (SCALING folded).
// ---------------------------------------------------------------------------
__global__ __launch_bounds__(256) void liquid_kernel(
    const float* __restrict__ lora_B,
    const float* __restrict__ hidden0,
    const float* __restrict__ W_gate, const float* __restrict__ b_gate,
    const float* __restrict__ W_tau,  const float* __restrict__ b_tau,
    int O)
{
    extern __shared__ float WT[];            // 128 * 132 floats
    __shared__ float inp_s[4][4][64];

    int t = threadIdx.x;
    for (int idx = t; idx < 64 * 128; idx += 256) {
        int r = idx >> 7;
        int k = idx & 127;
        WT[k * 132 + r]      = W_gate[idx];
        WT[k * 132 + 64 + r] = W_tau[idx];
    }
    __syncthreads();

    int g = t >> 6;
    int r = t & 63;
    int group_id = blockIdx.x * 4 + g;
    int stride   = gridDim.x * 4 * 4;        // rows consumed per pass (all groups)
    int npass    = (O + stride - 1) / stride;

    float bg = b_gate[r];
    float bt = b_tau[r];

    for (int p = 0; p < npass; p++) {
        int o4 = (group_id + p * gridDim.x * 4) * 4;
        bool ok = (o4 < O);

        float tgt[4], pg[4], pt[4], h[4];
        #pragma unroll
        for (int j = 0; j < 4; j++) {
            tgt[j] = ok ? lora_B[(size_t)(o4 + j) * RR + r] : 0.0f;
            h[j]   = ok ? hidden0[(size_t)(o4 + j) * RR + r] : 0.0f;
            pg[j] = bg; pt[j] = bt;
        }
        #pragma unroll
        for (int j = 0; j < 4; j++) inp_s[g][j][r] = tgt[j];
        __syncthreads();
        #pragma unroll 8
        for (int k = 0; k < 64; k++) {
            float wg = WT[k * 132 + r];
            float wt = WT[k * 132 + 64 + r];
            #pragma unroll
            for (int j = 0; j < 4; j++) {
                float v = inp_s[g][j][k];
                pg[j] += v * wg;
                pt[j] += v * wt;
            }
        }
        __syncthreads();

        #pragma unroll
        for (int step = 0; step < 3; step++) {
            #pragma unroll
            for (int j = 0; j < 4; j++) inp_s[g][j][r] = h[j];
            __syncthreads();
            float ga[4], ta[4];
            #pragma unroll
            for (int j = 0; j < 4; j++) { ga[j] = pg[j]; ta[j] = pt[j]; }
            #pragma unroll 8
            for (int k = 0; k < 64; k++) {
                float wg = WT[(64 + k) * 132 + r];
                float wt = WT[(64 + k) * 132 + 64 + r];
                #pragma unroll
                for (int j = 0; j < 4; j++) {
                    float v = inp_s[g][j][k];
                    ga[j] += v * wg;
                    ta[j] += v * wt;
                }
            }
            __syncthreads();
            #pragma unroll
            for (int j = 0; j < 4; j++) {
                float f    = 1.0f / (1.0f + expf(-ga[j]));
                float tau  = TAU_MIN_C + (TAU_MAX_C - TAU_MIN_C) / (1.0f + expf(-ta[j]));
                float a    = 1.0f / tau + f;
                float dec  = expf(-a * DT_C);
                h[j] = h[j] * dec + (f / a) * tgt[j] * (1.0f - dec);
            }
        }

        if (ok) {
            #pragma unroll
            for (int j = 0; j < 4; j++) {
                float v = SCALING_C * h[j];
                __nv_bfloat16 hb = __float2bfloat16_rn(v);
                float lo = v - __bfloat162float(hb);
                g_hB_hi[(size_t)(o4 + j) * RR + r] = hb;
                g_hB_lo[(size_t)(o4 + j) * RR + r] = __float2bfloat16_rn(lo);
            }
        }
    }
}

// ---------------------------------------------------------------------------
// Kernel 2: t = x @ A^T via mma.sync bf16 split (hi*hi + hi*lo + lo*hi).
// CTA tile 128(M) x 64(N=R), K-tiles of 64, DOUBLE-BUFFERED smem (2x48KB),
// single __syncthreads per iteration. 8 warps as 4(m) x 2(n), warp 32x32.
// Epilogue writes t pre-split to bf16 hi/lo.
// ---------------------------------------------------------------------------
#define G1_STAGE 49152
__global__ __launch_bounds__(256) void gemm1_mma(
    const float* __restrict__ x, const float* __restrict__ A, int M, int D)
{
    extern __shared__ char dsm[];
    uint32_t sb  = (smem_u32(dsm) + 1023) & ~1023u;
    // stage layout: xhi 16K | xlo 16K | ahi 8K | alo 8K
    int tid = threadIdx.x, wid = tid >> 5, lane = tid & 31;
    int warp_m = wid >> 1, warp_n = wid & 1;
    int tt = lane >> 3, rr = lane & 7;
    int g  = lane >> 2, tq = lane & 3;

    int m0 = blockIdx.x * 128;

    int xrow = tid >> 1, xcb = (tid & 1) * 32;
    int arow = tid >> 2, acb = (tid & 3) * 16;
    const float* xg = x + (size_t)(m0 + xrow) * D + xcb;
    const float* ag = A + (size_t)arow * D + acb;

    int a_row  = warp_m * 32 + (tt & 1) * 8 + rr;
    int a_colb = (tt >> 1) * 16;
    int b_row  = warp_n * 32 + (tt >> 1) * 8 + rr;
    int b_colb = (tt & 1) * 16;

    float acc[2][4][4];
    #pragma unroll
    for (int i = 0; i < 2; i++)
        #pragma unroll
        for (int j = 0; j < 4; j++)
            #pragma unroll
            for (int k = 0; k < 4; k++) acc[i][j][k] = 0.0f;

    float4 xv[8], av[4];
    #pragma unroll
    for (int j = 0; j < 8; j++) xv[j] = ((const float4*)xg)[j];
    #pragma unroll
    for (int j = 0; j < 4; j++) av[j] = ((const float4*)ag)[j];

    uint32_t x_sts = sw128((uint32_t)(xrow * 128 + xcb * 2));
    uint32_t a_sts = sw128((uint32_t)(arow * 128 + acb * 2));

    int nkt = D >> 6;
    for (int kt = 0; kt < nkt; kt++) {
        uint32_t st = sb + (kt & 1) * G1_STAGE;
        uint32_t xhi = st, xlo = st + 16384, ahi = st + 32768, alo = st + 40960;

        // store stage kt (regs already hold tile kt)
        #pragma unroll
        for (int j = 0; j < 4; j++) {
            uint32_t h0, l0, h1, l1, h2, l2, h3, l3;
            split2(xv[2*j].x,   xv[2*j].y,   h0, l0);
            split2(xv[2*j].z,   xv[2*j].w,   h1, l1);
            split2(xv[2*j+1].x, xv[2*j+1].y, h2, l2);
            split2(xv[2*j+1].z, xv[2*j+1].w, h3, l3);
            uint32_t off = sw128((uint32_t)(xrow * 128 + xcb * 2 + j * 16));
            sts128(xhi + off, h0, h1, h2, h3);
            sts128(xlo + off, l0, l1, l2, l3);
        }
        #pragma unroll
        for (int j = 0; j < 2; j++) {
            uint32_t h0, l0, h1, l1, h2, l2, h3, l3;
            split2(av[2*j].x,   av[2*j].y,   h0, l0);
            split2(av[2*j].z,   av[2*j].w,   h1, l1);
            split2(av[2*j+1].x, av[2*j+1].y, h2, l2);
            split2(av[2*j+1].z, av[2*j+1].w, h3, l3);
            uint32_t off = sw128((uint32_t)(arow * 128 + acb * 2 + j * 16));
            sts128(ahi + off, h0, h1, h2, h3);
            sts128(alo + off, l0, l1, l2, l3);
        }
        __syncthreads();   // separates ldmatrix(kt-1) from STS(kt+1) too

        if (kt + 1 < nkt) {     // prefetch next tile; hidden by MMAs below
            const float4* xp = (const float4*)(xg + (size_t)(kt + 1) * 64);
            #pragma unroll
            for (int j = 0; j < 8; j++) xv[j] = xp[j];
            const float4* ap = (const float4*)(ag + (size_t)(kt + 1) * 64);
            #pragma unroll
            for (int j = 0; j < 4; j++) av[j] = ap[j];
        }

        #pragma unroll
        for (int kk = 0; kk < 4; kk++) {
            uint32_t axh[2][4], axl[2][4];
            #pragma unroll
            for (int mt = 0; mt < 2; mt++) {
                uint32_t off = sw128((uint32_t)((a_row + mt * 16) * 128 + a_colb + kk * 32));
                ldm_x4(axh[mt], xhi + off);
                ldm_x4(axl[mt], xlo + off);
            }
            uint32_t bh[4][2], bl[4][2];
            #pragma unroll
            for (int np = 0; np < 2; np++) {
                uint32_t off = sw128((uint32_t)((b_row + np * 16) * 128 + b_colb + kk * 32));
                uint32_t r4[4];
                ldm_x4(r4, ahi + off);
                bh[2*np][0] = r4[0]; bh[2*np][1] = r4[1];
                bh[2*np+1][0] = r4[2]; bh[2*np+1][1] = r4[3];
                ldm_x4(r4, alo + off);
                bl[2*np][0] = r4[0]; bl[2*np][1] = r4[1];
                bl[2*np+1][0] = r4[2]; bl[2*np+1][1] = r4[3];
            }
            #pragma unroll
            for (int mt = 0; mt < 2; mt++)
                #pragma unroll
                for (int nt = 0; nt < 4; nt++) {
                    mma16816(acc[mt][nt], axh[mt], bh[nt]);
                    mma16816(acc[mt][nt], axh[mt], bl[nt]);
                    mma16816(acc[mt][nt], axl[mt], bh[nt]);
                }
        }
    }

    // epilogue: split t into bf16 hi/lo
    #pragma unroll
    for (int mt = 0; mt < 2; mt++) {
        int m = m0 + warp_m * 32 + mt * 16 + g;
        #pragma unroll
        for (int nt = 0; nt < 4; nt++) {
            int n = warp_n * 32 + nt * 8 + 2 * tq;
            uint32_t hi, lo;
            split2(acc[mt][nt][0], acc[mt][nt][1], hi, lo);
            *(uint32_t*)(g_t_hi + (size_t)m * RR + n) = hi;
            *(uint32_t*)(g_t_lo + (size_t)m * RR + n) = lo;
            split2(acc[mt][nt][2], acc[mt][nt][3], hi, lo);
            *(uint32_t*)(g_t_hi + (size_t)(m + 8) * RR + n) = hi;
            *(uint32_t*)(g_t_lo + (size_t)(m + 8) * RR + n) = lo;
        }
    }
}

// ---------------------------------------------------------------------------
// Kernel 3: out = t @ Beff^T (SCALING folded into Beff), K = 64 single shot.
// CTA tile 128(M) x 128(O). 8 warps as 2(m) x 4(n), warp tile 64x32.
// ---------------------------------------------------------------------------
__global__ __launch_bounds__(256) void gemm2_mma(
    float* __restrict__ out, int M, int O)
{
    extern __shared__ char dsm[];
    uint32_t sb  = (smem_u32(dsm) + 1023) & ~1023u;
    uint32_t thi = sb;                 // 128 rows * 128B
    uint32_t tlo = sb + 16384;
    uint32_t hhi = sb + 32768;         // 128 rows * 128B
    uint32_t hlo = sb + 49152;

    int tid = threadIdx.x, wid = tid >> 5, lane = tid & 31;
    int warp_m = wid & 1, warp_n = wid >> 1;
    int tt = lane >> 3, rr = lane & 7;
    int g  = lane >> 2, tq = lane & 3;

    int m0 = blockIdx.x * 128;
    int o0 = blockIdx.y * 128;

    // t tiles: 128 rows x 8 x16B chunks -> 4 chunks/thread/array
    #pragma unroll
    for (int j = 0; j < 4; j++) {
        int i = tid + 256 * j;
        int row = i >> 3, c = i & 7;
        uint4 vh = ((const uint4*)(g_t_hi + (size_t)(m0 + row) * RR))[c];
        uint4 vl = ((const uint4*)(g_t_lo + (size_t)(m0 + row) * RR))[c];
        uint32_t off = sw128((uint32_t)(row * 128 + c * 16));
        sts128(thi + off, vh.x, vh.y, vh.z, vh.w);
        sts128(tlo + off, vl.x, vl.y, vl.z, vl.w);
    }
    // h tiles: 128 rows x 8 chunks -> 4 chunks/thread/array
    #pragma unroll
    for (int j = 0; j < 4; j++) {
        int i = tid + 256 * j;
        int row = i >> 3, c = i & 7;
        uint4 vh = ((const uint4*)(g_hB_hi + (size_t)(o0 + row) * RR))[c];
        uint4 vl = ((const uint4*)(g_hB_lo + (size_t)(o0 + row) * RR))[c];
        uint32_t off = sw128((uint32_t)(row * 128 + c * 16));
        sts128(hhi + off, vh.x, vh.y, vh.z, vh.w);
        sts128(hlo + off, vl.x, vl.y, vl.z, vl.w);
    }
    __syncthreads();

    int a_row  = warp_m * 64 + (tt & 1) * 8 + rr;   // + mt*16 (4 m-frags)
    int a_colb = (tt >> 1) * 16;
    int b_row  = warp_n * 32 + (tt >> 1) * 8 + rr;  // + np*16 (2 -> 4 n-frags)
    int b_colb = (tt & 1) * 16;

    float acc[4][4][4];
    #pragma unroll
    for (int i = 0; i < 4; i++)
        #pragma unroll
        for (int j = 0; j < 4; j++)
            #pragma unroll
            for (int k = 0; k < 4; k++) acc[i][j][k] = 0.0f;

    #pragma unroll
    for (int kk = 0; kk < 4; kk++) {
        uint32_t axh[4][4], axl[4][4];
        #pragma unroll
        for (int mt = 0; mt < 4; mt++) {
            uint32_t off = sw128((uint32_t)((a_row + mt * 16) * 128 + a_colb + kk * 32));
            ldm_x4(axh[mt], thi + off);
            ldm_x4(axl[mt], tlo + off);
        }
        uint32_t bh[4][2], bl[4][2];
        #pragma unroll
        for (int np = 0; np < 2; np++) {
            uint32_t off = sw128((uint32_t)((b_row + np * 16) * 128 + b_colb + kk * 32));
            uint32_t r4[4];
            ldm_x4(r4, hhi + off);
            bh[2*np][0] = r4[0]; bh[2*np][1] = r4[1];
            bh[2*np+1][0] = r4[2]; bh[2*np+1][1] = r4[3];
            ldm_x4(r4, hlo + off);
            bl[2*np][0] = r4[0]; bl[2*np][1] = r4[1];
            bl[2*np+1][0] = r4[2]; bl[2*np+1][1] = r4[3];
        }
        #pragma unroll
        for (int mt = 0; mt < 4; mt++)
            #pragma unroll
            for (int nt = 0; nt < 4; nt++) {
                mma16816(acc[mt][nt], axh[mt], bh[nt]);
                mma16816(acc[mt][nt], axh[mt], bl[nt]);
                mma16816(acc[mt][nt], axl[mt], bh[nt]);
            }
    }

    #pragma unroll
    for (int mt = 0; mt < 4; mt++) {
        int m = m0 + warp_m * 64 + mt * 16 + g;
        #pragma unroll
        for (int nt = 0; nt < 4; nt++) {
            int o = o0 + warp_n * 32 + nt * 8 + 2 * tq;
            float2 v0 = make_float2(acc[mt][nt][0], acc[mt][nt][1]);
            *(float2*)(out + (size_t)m * O + o) = v0;
            float2 v1 = make_float2(acc[mt][nt][2], acc[mt][nt][3]);
            *(float2*)(out + (size_t)(m + 8) * O + o) = v1;
        }
    }
}

// ---------------------------------------------------------------------------
extern "C" void kernel_launch(void* const* d_in, const int* in_sizes, int n_in,
                              void* d_out, int out_size)
{
    const float* x       = (const float*)d_in[0];
    const float* lora_A  = (const float*)d_in[1];
    const float* lora_B  = (const float*)d_in[2];
    const float* hidden0 = (const float*)d_in[3];
    const float* W_gate  = (const float*)d_in[4];
    const float* b_gate  = (const float*)d_in[5];
    const float* W_tau   = (const float*)d_in[6];
    const float* b_tau   = (const float*)d_in[7];
    float* out = (float*)d_out;

    int R = in_sizes[5];                 // 64
    int D = in_sizes[1] / R;             // 4096
    int O = in_sizes[2] / R;             // 4096
    int M = in_sizes[0] / D;             // 16384

    cudaFuncSetAttribute(liquid_kernel,
                         cudaFuncAttributeMaxDynamicSharedMemorySize,
                         128 * 132 * (int)sizeof(float));
    cudaFuncSetAttribute(gemm1_mma,
                         cudaFuncAttributeMaxDynamicSharedMemorySize, 2 * G1_STAGE + 1024);
    cudaFuncSetAttribute(gemm2_mma,
                         cudaFuncAttributeMaxDynamicSharedMemorySize, 66560);

    liquid_kernel<<<128, 256, 128 * 132 * sizeof(float)>>>(
        lora_B, hidden0, W_gate, b_gate, W_tau, b_tau, O);

    gemm1_mma<<<M / 128, 256, 2 * G1_STAGE + 1024>>>(x, lora_A, M, D);

    dim3 g2(M / 128, O / 128);
    gemm2_mma<<<g2, 256, 66560>>>(out, M, O);
}

// round 8
// speedup vs baseline: 2.9971x; 1.1422x over previous
#include <cuda_runtime.h>
#include <cuda_bf16.h>
#include <math.h>
#include <stdint.h>

#define RR 64
#define DT_C 0.1f
#define TAU_MIN_C 0.1f
#define TAU_MAX_C 10.0f
#define SCALING_C 2.0f          // 128/64

#define MAX_M 16384
#define MAX_O 4096

// scratch (device globals: no allocation allowed)
__device__ __align__(16) __nv_bfloat16 g_t_hi[MAX_M * RR];   // 2 MB
__device__ __align__(16) __nv_bfloat16 g_t_lo[MAX_M * RR];   // 2 MB
__device__ __align__(16) __nv_bfloat16 g_hB_hi[MAX_O * RR];  // split of 2*hidden
__device__ __align__(16) __nv_bfloat16 g_hB_lo[MAX_O * RR];

// ---------------------------------------------------------------------------
// helpers
// ---------------------------------------------------------------------------
__device__ __forceinline__ uint32_t smem_u32(const void* p) {
    uint32_t a;
    asm("{ .reg .u64 t; cvta.to.shared.u64 t, %1; cvt.u32.u64 %0, t; }"
        : "=r"(a) : "l"(p));
    return a;
}
__device__ __forceinline__ uint32_t sw128(uint32_t o) { return o ^ ((o >> 3) & 0x70); }

__device__ __forceinline__ void sts128(uint32_t a, uint32_t x, uint32_t y,
                                       uint32_t z, uint32_t w) {
    asm volatile("st.shared.v4.b32 [%0], {%1,%2,%3,%4};"
                 :: "r"(a), "r"(x), "r"(y), "r"(z), "r"(w) : "memory");
}
__device__ __forceinline__ void ldm_x4(uint32_t* r, uint32_t addr) {
    asm volatile("ldmatrix.sync.aligned.m8n8.x4.shared.b16 {%0,%1,%2,%3}, [%4];"
                 : "=r"(r[0]), "=r"(r[1]), "=r"(r[2]), "=r"(r[3]) : "r"(addr));
}
// D += A * B, bf16 inputs, fp32 accum (register-path tensor core, sm_80+)
__device__ __forceinline__ void mma16816(float* d, const uint32_t* a, const uint32_t* b) {
    asm volatile(
        "mma.sync.aligned.m16n8k16.row.col.f32.bf16.bf16.f32 "
        "{%0,%1,%2,%3}, {%4,%5,%6,%7}, {%8,%9}, {%0,%1,%2,%3};"
        : "+f"(d[0]), "+f"(d[1]), "+f"(d[2]), "+f"(d[3])
        : "r"(a[0]), "r"(a[1]), "r"(a[2]), "r"(a[3]), "r"(b[0]), "r"(b[1]));
}
// split a pair of fp32 into hi/lo bf16x2 (packed, element order preserved)
__device__ __forceinline__ void split2(float a, float b, uint32_t& hi, uint32_t& lo) {
    __nv_bfloat162 h = __floats2bfloat162_rn(a, b);
    float2 hf = __bfloat1622float2(h);
    __nv_bfloat162 l = __floats2bfloat162_rn(a - hf.x, b - hf.y);
    hi = *reinterpret_cast<uint32_t*>(&h);
    lo = *reinterpret_cast<uint32_t*>(&l);
}

// ---------------------------------------------------------------------------
// Kernel 1: liquid dynamics, warp-shuffle form. Each warp owns 4 rows; lane
// owns features (lane) and (lane+32). h-broadcast via shfl — NO inner
// __syncthreads. 16 independent FMA chains per lane.
// Writes B_eff = 2*hidden_new pre-split into bf16 hi/lo (SCALING folded).
// ---------------------------------------------------------------------------
__global__ __launch_bounds__(256) void liquid_kernel(
    const float* __restrict__ lora_B,
    const float* __restrict__ hidden0,
    const float* __restrict__ W_gate, const float* __restrict__ b_gate,
    const float* __restrict__ W_tau,  const float* __restrict__ b_tau,
    int O)
{
    extern __shared__ float WT[];            // 128 * 132 floats

    int t = threadIdx.x;
    // transpose-load both weight matrices [64][128] -> WT[k][c]
    // c in [0,64): gate col c ; c in [64,128): tau col c-64
    for (int idx = t; idx < 64 * 128; idx += 256) {
        int r = idx >> 7;
        int k = idx & 127;
        WT[k * 132 + r]      = W_gate[idx];
        WT[k * 132 + 64 + r] = W_tau[idx];
    }
    __syncthreads();

    int lane = t & 31, w = t >> 5;
    int o4 = (blockIdx.x * 8 + w) * 4;
    if (o4 >= O) return;

    float bg0 = b_gate[lane],      bg1 = b_gate[lane + 32];
    float bt0 = b_tau[lane],       bt1 = b_tau[lane + 32];

    float tg0[4], tg1[4], h0[4], h1[4];
    #pragma unroll
    for (int j = 0; j < 4; j++) {
        tg0[j] = lora_B[(size_t)(o4 + j) * RR + lane];
        tg1[j] = lora_B[(size_t)(o4 + j) * RR + lane + 32];
        h0[j]  = hidden0[(size_t)(o4 + j) * RR + lane];
        h1[j]  = hidden0[(size_t)(o4 + j) * RR + lane + 32];
    }

    // target-half partial dots (inp columns 0..63)
    float pg0[4], pg1[4], pt0[4], pt1[4];
    #pragma unroll
    for (int j = 0; j < 4; j++) { pg0[j] = bg0; pg1[j] = bg1; pt0[j] = bt0; pt1[j] = bt1; }
    #pragma unroll 8
    for (int k = 0; k < 32; k++) {
        float wg0 = WT[k * 132 + lane],      wg1 = WT[k * 132 + lane + 32];
        float wt0 = WT[k * 132 + 64 + lane], wt1 = WT[k * 132 + 96 + lane];
        float wg0b = WT[(k + 32) * 132 + lane],      wg1b = WT[(k + 32) * 132 + lane + 32];
        float wt0b = WT[(k + 32) * 132 + 64 + lane], wt1b = WT[(k + 32) * 132 + 96 + lane];
        #pragma unroll
        for (int j = 0; j < 4; j++) {
            float v  = __shfl_sync(0xffffffffu, tg0[j], k);
            float v2 = __shfl_sync(0xffffffffu, tg1[j], k);
            pg0[j] += v * wg0;  pg1[j] += v * wg1;
            pt0[j] += v * wt0;  pt1[j] += v * wt1;
            pg0[j] += v2 * wg0b; pg1[j] += v2 * wg1b;
            pt0[j] += v2 * wt0b; pt1[j] += v2 * wt1b;
        }
    }

    #pragma unroll
    for (int step = 0; step < 3; step++) {
        float ga0[4], ga1[4], ta0[4], ta1[4];
        #pragma unroll
        for (int j = 0; j < 4; j++) { ga0[j] = pg0[j]; ga1[j] = pg1[j]; ta0[j] = pt0[j]; ta1[j] = pt1[j]; }
        #pragma unroll 8
        for (int k = 0; k < 32; k++) {
            float wg0 = WT[(64 + k) * 132 + lane],      wg1 = WT[(64 + k) * 132 + lane + 32];
            float wt0 = WT[(64 + k) * 132 + 64 + lane], wt1 = WT[(64 + k) * 132 + 96 + lane];
            float wg0b = WT[(96 + k) * 132 + lane],      wg1b = WT[(96 + k) * 132 + lane + 32];
            float wt0b = WT[(96 + k) * 132 + 64 + lane], wt1b = WT[(96 + k) * 132 + 96 + lane];
            #pragma unroll
            for (int j = 0; j < 4; j++) {
                float v  = __shfl_sync(0xffffffffu, h0[j], k);
                float v2 = __shfl_sync(0xffffffffu, h1[j], k);
                ga0[j] += v * wg0;  ga1[j] += v * wg1;
                ta0[j] += v * wt0;  ta1[j] += v * wt1;
                ga0[j] += v2 * wg0b; ga1[j] += v2 * wg1b;
                ta0[j] += v2 * wt0b; ta1[j] += v2 * wt1b;
            }
        }
        #pragma unroll
        for (int j = 0; j < 4; j++) {
            float f0   = 1.0f / (1.0f + expf(-ga0[j]));
            float f1   = 1.0f / (1.0f + expf(-ga1[j]));
            float tau0 = TAU_MIN_C + (TAU_MAX_C - TAU_MIN_C) / (1.0f + expf(-ta0[j]));
            float tau1 = TAU_MIN_C + (TAU_MAX_C - TAU_MIN_C) / (1.0f + expf(-ta1[j]));
            float a0   = 1.0f / tau0 + f0;
            float a1   = 1.0f / tau1 + f1;
            float d0   = expf(-a0 * DT_C);
            float d1   = expf(-a1 * DT_C);
            h0[j] = h0[j] * d0 + (f0 / a0) * tg0[j] * (1.0f - d0);
            h1[j] = h1[j] * d1 + (f1 / a1) * tg1[j] * (1.0f - d1);
        }
    }

    #pragma unroll
    for (int j = 0; j < 4; j++) {
        float v0 = SCALING_C * h0[j];
        float v1 = SCALING_C * h1[j];
        __nv_bfloat16 b0 = __float2bfloat16_rn(v0);
        __nv_bfloat16 b1 = __float2bfloat16_rn(v1);
        g_hB_hi[(size_t)(o4 + j) * RR + lane]      = b0;
        g_hB_hi[(size_t)(o4 + j) * RR + lane + 32] = b1;
        g_hB_lo[(size_t)(o4 + j) * RR + lane]      = __float2bfloat16_rn(v0 - __bfloat162float(b0));
        g_hB_lo[(size_t)(o4 + j) * RR + lane + 32] = __float2bfloat16_rn(v1 - __bfloat162float(b1));
    }
}

// ---------------------------------------------------------------------------
// Kernel 2: t = x @ A^T via mma.sync bf16 split (hi*hi + hi*lo + lo*hi).
// CTA tile 64(M) x 64(N=R), K-tiles of 64, double-buffered smem (2x32KB),
// one __syncthreads per iteration, 2 CTAs/SM (all 256 CTAs resident).
// 8 warps as 4(m) x 2(n), warp tile 16x32.
// ---------------------------------------------------------------------------
#define G1_STAGE 32768
__global__ __launch_bounds__(256, 2) void gemm1_mma(
    const float* __restrict__ x, const float* __restrict__ A, int M, int D)
{
    extern __shared__ char dsm[];
    uint32_t sb  = (smem_u32(dsm) + 1023) & ~1023u;
    // stage layout: xhi 8K | xlo 8K | ahi 8K | alo 8K
    int tid = threadIdx.x, wid = tid >> 5, lane = tid & 31;
    int warp_m = wid >> 1, warp_n = wid & 1;
    int tt = lane >> 3, rr = lane & 7;
    int g  = lane >> 2, tq = lane & 3;

    int m0 = blockIdx.x * 64;

    // staging: 64 rows, 4 threads/row, 16 floats each (both x and A)
    int srow = tid >> 2, scb = (tid & 3) * 16;
    const float* xg = x + (size_t)(m0 + srow) * D + scb;
    const float* ag = A + (size_t)srow * D + scb;

    int a_row  = warp_m * 16 + (tt & 1) * 8 + rr;
    int a_colb = (tt >> 1) * 16;
    int b_row  = warp_n * 32 + (tt >> 1) * 8 + rr;
    int b_colb = (tt & 1) * 16;

    float acc[4][4];
    #pragma unroll
    for (int j = 0; j < 4; j++)
        #pragma unroll
        for (int k = 0; k < 4; k++) acc[j][k] = 0.0f;

    float4 xv[4], av[4];
    #pragma unroll
    for (int j = 0; j < 4; j++) xv[j] = ((const float4*)xg)[j];
    #pragma unroll
    for (int j = 0; j < 4; j++) av[j] = ((const float4*)ag)[j];

    int nkt = D >> 6;
    for (int kt = 0; kt < nkt; kt++) {
        uint32_t st = sb + (kt & 1) * G1_STAGE;
        uint32_t xhi = st, xlo = st + 8192, ahi = st + 16384, alo = st + 24576;

        // store stage kt (regs already hold tile kt)
        #pragma unroll
        for (int j = 0; j < 2; j++) {
            uint32_t h0, l0, h1, l1, h2, l2, h3, l3;
            split2(xv[2*j].x,   xv[2*j].y,   h0, l0);
            split2(xv[2*j].z,   xv[2*j].w,   h1, l1);
            split2(xv[2*j+1].x, xv[2*j+1].y, h2, l2);
            split2(xv[2*j+1].z, xv[2*j+1].w, h3, l3);
            uint32_t off = sw128((uint32_t)(srow * 128 + scb * 2 + j * 16));
            sts128(xhi + off, h0, h1, h2, h3);
            sts128(xlo + off, l0, l1, l2, l3);
            split2(av[2*j].x,   av[2*j].y,   h0, l0);
            split2(av[2*j].z,   av[2*j].w,   h1, l1);
            split2(av[2*j+1].x, av[2*j+1].y, h2, l2);
            split2(av[2*j+1].z, av[2*j+1].w, h3, l3);
            sts128(ahi + off, h0, h1, h2, h3);
            sts128(alo + off, l0, l1, l2, l3);
        }
        __syncthreads();

        if (kt + 1 < nkt) {     // prefetch next tile; hidden by MMAs below
            const float4* xp = (const float4*)(xg + (size_t)(kt + 1) * 64);
            #pragma unroll
            for (int j = 0; j < 4; j++) xv[j] = xp[j];
            const float4* ap = (const float4*)(ag + (size_t)(kt + 1) * 64);
            #pragma unroll
            for (int j = 0; j < 4; j++) av[j] = ap[j];
        }

        #pragma unroll
        for (int kk = 0; kk < 4; kk++) {
            uint32_t bh[4][2], bl[4][2];
            #pragma unroll
            for (int np = 0; np < 2; np++) {
                uint32_t off = sw128((uint32_t)((b_row + np * 16) * 128 + b_colb + kk * 32));
                uint32_t r4[4];
                ldm_x4(r4, ahi + off);
                bh[2*np][0] = r4[0]; bh[2*np][1] = r4[1];
                bh[2*np+1][0] = r4[2]; bh[2*np+1][1] = r4[3];
                ldm_x4(r4, alo + off);
                bl[2*np][0] = r4[0]; bl[2*np][1] = r4[1];
                bl[2*np+1][0] = r4[2]; bl[2*np+1][1] = r4[3];
            }
            uint32_t axh[4], axl[4];
            {
                uint32_t off = sw128((uint32_t)(a_row * 128 + a_colb + kk * 32));
                ldm_x4(axh, xhi + off);
                ldm_x4(axl, xlo + off);
            }
            #pragma unroll
            for (int nt = 0; nt < 4; nt++) {
                mma16816(acc[nt], axh, bh[nt]);
                mma16816(acc[nt], axh, bl[nt]);
                mma16816(acc[nt], axl, bh[nt]);
            }
        }
    }

    // epilogue: split t into bf16 hi/lo
    int m = m0 + warp_m * 16 + g;
    #pragma unroll
    for (int nt = 0; nt < 4; nt++) {
        int n = warp_n * 32 + nt * 8 + 2 * tq;
        uint32_t hi, lo;
        split2(acc[nt][0], acc[nt][1], hi, lo);
        *(uint32_t*)(g_t_hi + (size_t)m * RR + n) = hi;
        *(uint32_t*)(g_t_lo + (size_t)m * RR + n) = lo;
        split2(acc[nt][2], acc[nt][3], hi, lo);
        *(uint32_t*)(g_t_hi + (size_t)(m + 8) * RR + n) = hi;
        *(uint32_t*)(g_t_lo + (size_t)(m + 8) * RR + n) = lo;
    }
}

// ---------------------------------------------------------------------------
// Kernel 3: out = t @ Beff^T (SCALING folded into Beff), K = 64 single shot.
// CTA tile 128(M) x 128(O), 2 CTAs/SM. 8 warps as 2(m) x 4(n), warp 64x32.
// B-frags hoisted per kk; A-frags short-lived (register pressure <= 128).
// ---------------------------------------------------------------------------
__global__ __launch_bounds__(256, 2) void gemm2_mma(
    float* __restrict__ out, int M, int O)
{
    extern __shared__ char dsm[];
    uint32_t sb  = (smem_u32(dsm) + 1023) & ~1023u;
    uint32_t thi = sb;                 // 128 rows * 128B
    uint32_t tlo = sb + 16384;
    uint32_t hhi = sb + 32768;         // 128 rows * 128B
    uint32_t hlo = sb + 49152;

    int tid = threadIdx.x, wid = tid >> 5, lane = tid & 31;
    int warp_m = wid & 1, warp_n = wid >> 1;
    int tt = lane >> 3, rr = lane & 7;
    int g  = lane >> 2, tq = lane & 3;

    int m0 = blockIdx.x * 128;
    int o0 = blockIdx.y * 128;

    // t tiles: 128 rows x 8 x16B chunks -> 4 chunks/thread/array
    #pragma unroll
    for (int j = 0; j < 4; j++) {
        int i = tid + 256 * j;
        int row = i >> 3, c = i & 7;
        uint4 vh = ((const uint4*)(g_t_hi + (size_t)(m0 + row) * RR))[c];
        uint4 vl = ((const uint4*)(g_t_lo + (size_t)(m0 + row) * RR))[c];
        uint32_t off = sw128((uint32_t)(row * 128 + c * 16));
        sts128(thi + off, vh.x, vh.y, vh.z, vh.w);
        sts128(tlo + off, vl.x, vl.y, vl.z, vl.w);
    }
    // h tiles: 128 rows x 8 chunks -> 4 chunks/thread/array
    #pragma unroll
    for (int j = 0; j < 4; j++) {
        int i = tid + 256 * j;
        int row = i >> 3, c = i & 7;
        uint4 vh = ((const uint4*)(g_hB_hi + (size_t)(o0 + row) * RR))[c];
        uint4 vl = ((const uint4*)(g_hB_lo + (size_t)(o0 + row) * RR))[c];
        uint32_t off = sw128((uint32_t)(row * 128 + c * 16));
        sts128(hhi + off, vh.x, vh.y, vh.z, vh.w);
        sts128(hlo + off, vl.x, vl.y, vl.z, vl.w);
    }
    __syncthreads();

    int a_row  = warp_m * 64 + (tt & 1) * 8 + rr;   // + mt*16 (4 m-frags)
    int a_colb = (tt >> 1) * 16;
    int b_row  = warp_n * 32 + (tt >> 1) * 8 + rr;  // + np*16 (2 -> 4 n-frags)
    int b_colb = (tt & 1) * 16;

    float acc[4][4][4];
    #pragma unroll
    for (int i = 0; i < 4; i++)
        #pragma unroll
        for (int j = 0; j < 4; j++)
            #pragma unroll
            for (int k = 0; k < 4; k++) acc[i][j][k] = 0.0f;

    #pragma unroll
    for (int kk = 0; kk < 4; kk++) {
        uint32_t bh[4][2], bl[4][2];
        #pragma unroll
        for (int np = 0; np < 2; np++) {
            uint32_t off = sw128((uint32_t)((b_row + np * 16) * 128 + b_colb + kk * 32));
            uint32_t r4[4];
            ldm_x4(r4, hhi + off);
            bh[2*np][0] = r4[0]; bh[2*np][1] = r4[1];
            bh[2*np+1][0] = r4[2]; bh[2*np+1][1] = r4[3];
            ldm_x4(r4, hlo + off);
            bl[2*np][0] = r4[0]; bl[2*np][1] = r4[1];
            bl[2*np+1][0] = r4[2]; bl[2*np+1][1] = r4[3];
        }
        #pragma unroll
        for (int mt = 0; mt < 4; mt++) {
            uint32_t axh[4], axl[4];
            uint32_t off = sw128((uint32_t)((a_row + mt * 16) * 128 + a_colb + kk * 32));
            ldm_x4(axh, thi + off);
            ldm_x4(axl, tlo + off);
            #pragma unroll
            for (int nt = 0; nt < 4; nt++) {
                mma16816(acc[mt][nt], axh, bh[nt]);
                mma16816(acc[mt][nt], axh, bl[nt]);
                mma16816(acc[mt][nt], axl, bh[nt]);
            }
        }
    }

    #pragma unroll
    for (int mt = 0; mt < 4; mt++) {
        int m = m0 + warp_m * 64 + mt * 16 + g;
        #pragma unroll
        for (int nt = 0; nt < 4; nt++) {
            int o = o0 + warp_n * 32 + nt * 8 + 2 * tq;
            float2 v0 = make_float2(acc[mt][nt][0], acc[mt][nt][1]);
            *(float2*)(out + (size_t)m * O + o) = v0;
            float2 v1 = make_float2(acc[mt][nt][2], acc[mt][nt][3]);
            *(float2*)(out + (size_t)(m + 8) * O + o) = v1;
        }
    }
}

// ---------------------------------------------------------------------------
extern "C" void kernel_launch(void* const* d_in, const int* in_sizes, int n_in,
                              void* d_out, int out_size)
{
    const float* x       = (const float*)d_in[0];
    const float* lora_A  = (const float*)d_in[1];
    const float* lora_B  = (const float*)d_in[2];
    const float* hidden0 = (const float*)d_in[3];
    const float* W_gate  = (const float*)d_in[4];
    const float* b_gate  = (const float*)d_in[5];
    const float* W_tau   = (const float*)d_in[6];
    const float* b_tau   = (const float*)d_in[7];
    float* out = (float*)d_out;

    int R = in_sizes[5];                 // 64
    int D = in_sizes[1] / R;             // 4096
    int O = in_sizes[2] / R;             // 4096
    int M = in_sizes[0] / D;             // 16384

    cudaFuncSetAttribute(liquid_kernel,
                         cudaFuncAttributeMaxDynamicSharedMemorySize,
                         128 * 132 * (int)sizeof(float));
    cudaFuncSetAttribute(gemm1_mma,
                         cudaFuncAttributeMaxDynamicSharedMemorySize, 2 * G1_STAGE + 1024);
    cudaFuncSetAttribute(gemm2_mma,
                         cudaFuncAttributeMaxDynamicSharedMemorySize, 66560);

    liquid_kernel<<<(O + 31) / 32, 256, 128 * 132 * sizeof(float)>>>(
        lora_B, hidden0, W_gate, b_gate, W_tau, b_tau, O);

    gemm1_mma<<<M / 64, 256, 2 * G1_STAGE + 1024>>>(x, lora_A, M, D);

    dim3 g2(M / 128, O / 128);
    gemm2_mma<<<g2, 256, 66560>>>(out, M, O);
}

// round 9
// speedup vs baseline: 3.3539x; 1.1190x over previous
#include <cuda_runtime.h>
#include <cuda_fp16.h>
#include <math.h>
#include <stdint.h>

#define RR 64
#define DT_C 0.1f
#define TAU_MIN_C 0.1f
#define TAU_MAX_C 10.0f
#define SCALING_C 2.0f          // 128/64

#define MAX_M 16384
#define MAX_O 4096

// scratch (device globals: no allocation allowed)
__device__ __align__(16) __half g_t_hi[MAX_M * RR];   // 2 MB
__device__ __align__(16) __half g_t_lo[MAX_M * RR];   // 2 MB
__device__ __align__(16) __half g_hB[MAX_O * RR];     // fp16 of 2*hidden

// ---------------------------------------------------------------------------
// helpers
// ---------------------------------------------------------------------------
__device__ __forceinline__ uint32_t smem_u32(const void* p) {
    uint32_t a;
    asm("{ .reg .u64 t; cvta.to.shared.u64 t, %1; cvt.u32.u64 %0, t; }"
        : "=r"(a) : "l"(p));
    return a;
}
__device__ __forceinline__ uint32_t sw128(uint32_t o) { return o ^ ((o >> 3) & 0x70); }

__device__ __forceinline__ void sts128(uint32_t a, uint32_t x, uint32_t y,
                                       uint32_t z, uint32_t w) {
    asm volatile("st.shared.v4.b32 [%0], {%1,%2,%3,%4};"
                 :: "r"(a), "r"(x), "r"(y), "r"(z), "r"(w) : "memory");
}
__device__ __forceinline__ void ldm_x4(uint32_t* r, uint32_t addr) {
    asm volatile("ldmatrix.sync.aligned.m8n8.x4.shared.b16 {%0,%1,%2,%3}, [%4];"
                 : "=r"(r[0]), "=r"(r[1]), "=r"(r[2]), "=r"(r[3]) : "r"(addr));
}
// D += A * B, fp16 inputs, fp32 accum
__device__ __forceinline__ void mma16816(float* d, const uint32_t* a, const uint32_t* b) {
    asm volatile(
        "mma.sync.aligned.m16n8k16.row.col.f32.f16.f16.f32 "
        "{%0,%1,%2,%3}, {%4,%5,%6,%7}, {%8,%9}, {%0,%1,%2,%3};"
        : "+f"(d[0]), "+f"(d[1]), "+f"(d[2]), "+f"(d[3])
        : "r"(a[0]), "r"(a[1]), "r"(a[2]), "r"(a[3]), "r"(b[0]), "r"(b[1]));
}
// split pair of fp32 into hi/lo fp16x2 (packed, element order preserved)
__device__ __forceinline__ void splitH(float a, float b, uint32_t& hi, uint32_t& lo) {
    __half2 h = __floats2half2_rn(a, b);
    float2 hf = __half22float2(h);
    __half2 l = __floats2half2_rn(a - hf.x, b - hf.y);
    hi = *reinterpret_cast<uint32_t*>(&h);
    lo = *reinterpret_cast<uint32_t*>(&l);
}
__device__ __forceinline__ uint32_t packH(float a, float b) {
    __half2 h = __floats2half2_rn(a, b);
    return *reinterpret_cast<uint32_t*>(&h);
}

// ---------------------------------------------------------------------------
// Fused kernel A:
//   blocks [0, nG1)      : GEMM1  t = x @ A^T  (fp16 2-product: (xh+xl)*Ah)
//   blocks [nG1, nG1+32) : liquid dynamics (overlapped; disjoint pipes)
// Dynamic smem 50176 B; __launch_bounds__(256,2) -> both paths co-resident.
// ---------------------------------------------------------------------------
#define G1_STAGE 24576
#define NLIQ 32

__global__ __launch_bounds__(256, 2) void fusedA(
    const float* __restrict__ x, const float* __restrict__ A,
    const float* __restrict__ lora_B, const float* __restrict__ hidden0,
    const float* __restrict__ W_gate, const float* __restrict__ b_gate,
    const float* __restrict__ W_tau,  const float* __restrict__ b_tau,
    int M, int D, int O, int nG1)
{
    extern __shared__ char dsm[];
    uint32_t sb = (smem_u32(dsm) + 1023) & ~1023u;
    int tid = threadIdx.x, wid = tid >> 5, lane = tid & 31;

    if ((int)blockIdx.x < nG1) {
        // ================= GEMM1 path: 64(M) x 64(N), K-tiles 64 =============
        int warp_m = wid >> 1, warp_n = wid & 1;
        int tt = lane >> 3, rr = lane & 7;
        int g  = lane >> 2, tq = lane & 3;

        int m0 = blockIdx.x * 64;
        int srow = tid >> 2, scb = (tid & 3) * 16;
        const float* xg = x + (size_t)(m0 + srow) * D + scb;
        const float* ag = A + (size_t)srow * D + scb;

        int a_row  = warp_m * 16 + (tt & 1) * 8 + rr;
        int a_colb = (tt >> 1) * 16;
        int b_row  = warp_n * 32 + (tt >> 1) * 8 + rr;
        int b_colb = (tt & 1) * 16;

        float acc[4][4];
        #pragma unroll
        for (int j = 0; j < 4; j++)
            #pragma unroll
            for (int k = 0; k < 4; k++) acc[j][k] = 0.0f;

        float4 xv[4], av[4];
        #pragma unroll
        for (int j = 0; j < 4; j++) xv[j] = ((const float4*)xg)[j];
        #pragma unroll
        for (int j = 0; j < 4; j++) av[j] = ((const float4*)ag)[j];

        int nkt = D >> 6;
        for (int kt = 0; kt < nkt; kt++) {
            uint32_t st = sb + (kt & 1) * G1_STAGE;
            uint32_t xhi = st, xlo = st + 8192, ahh = st + 16384;

            #pragma unroll
            for (int j = 0; j < 2; j++) {
                uint32_t h0, l0, h1, l1, h2, l2, h3, l3;
                splitH(xv[2*j].x,   xv[2*j].y,   h0, l0);
                splitH(xv[2*j].z,   xv[2*j].w,   h1, l1);
                splitH(xv[2*j+1].x, xv[2*j+1].y, h2, l2);
                splitH(xv[2*j+1].z, xv[2*j+1].w, h3, l3);
                uint32_t off = sw128((uint32_t)(srow * 128 + scb * 2 + j * 16));
                sts128(xhi + off, h0, h1, h2, h3);
                sts128(xlo + off, l0, l1, l2, l3);
                uint32_t a0 = packH(av[2*j].x,   av[2*j].y);
                uint32_t a1 = packH(av[2*j].z,   av[2*j].w);
                uint32_t a2 = packH(av[2*j+1].x, av[2*j+1].y);
                uint32_t a3 = packH(av[2*j+1].z, av[2*j+1].w);
                sts128(ahh + off, a0, a1, a2, a3);
            }
            __syncthreads();

            if (kt + 1 < nkt) {
                const float4* xp = (const float4*)(xg + (size_t)(kt + 1) * 64);
                #pragma unroll
                for (int j = 0; j < 4; j++) xv[j] = xp[j];
                const float4* ap = (const float4*)(ag + (size_t)(kt + 1) * 64);
                #pragma unroll
                for (int j = 0; j < 4; j++) av[j] = ap[j];
            }

            #pragma unroll
            for (int kk = 0; kk < 4; kk++) {
                uint32_t bh[4][2];
                #pragma unroll
                for (int np = 0; np < 2; np++) {
                    uint32_t off = sw128((uint32_t)((b_row + np * 16) * 128 + b_colb + kk * 32));
                    uint32_t r4[4];
                    ldm_x4(r4, ahh + off);
                    bh[2*np][0] = r4[0]; bh[2*np][1] = r4[1];
                    bh[2*np+1][0] = r4[2]; bh[2*np+1][1] = r4[3];
                }
                uint32_t axh[4], axl[4];
                uint32_t off = sw128((uint32_t)(a_row * 128 + a_colb + kk * 32));
                ldm_x4(axh, xhi + off);
                ldm_x4(axl, xlo + off);
                #pragma unroll
                for (int nt = 0; nt < 4; nt++) {
                    mma16816(acc[nt], axh, bh[nt]);
                    mma16816(acc[nt], axl, bh[nt]);
                }
            }
        }

        int m = m0 + warp_m * 16 + g;
        #pragma unroll
        for (int nt = 0; nt < 4; nt++) {
            int n = warp_n * 32 + nt * 8 + 2 * tq;
            uint32_t hi, lo;
            splitH(acc[nt][0], acc[nt][1], hi, lo);
            *(uint32_t*)(g_t_hi + (size_t)m * RR + n) = hi;
            *(uint32_t*)(g_t_lo + (size_t)m * RR + n) = lo;
            splitH(acc[nt][2], acc[nt][3], hi, lo);
            *(uint32_t*)(g_t_hi + (size_t)(m + 8) * RR + n) = hi;
            *(uint32_t*)(g_t_lo + (size_t)(m + 8) * RR + n) = lo;
        }
    } else {
        // ================= liquid path (shfl form, h-half weights in smem) ===
        float* WT2 = (float*)(dsm + 1024);   // [64][132]: k2 in 0..63 (k=64+k2)
        // load h-half of both weight matrices, transposed
        for (int idx = tid; idx < 128 * 64; idx += 256) {
            int r = idx >> 6, k2 = idx & 63;
            if (r < 64) WT2[k2 * 132 + r]        = W_gate[r * 128 + 64 + k2];
            else        WT2[k2 * 132 + 64 + (r - 64)] = W_tau[(r - 64) * 128 + 64 + k2];
        }
        __syncthreads();

        int lb = blockIdx.x - nG1;                   // 0..NLIQ-1
        int gw = lb * 8 + wid;                       // 0..255
        int rows_per_warp = O / (NLIQ * 8);          // 16
        int base = gw * rows_per_warp;

        float bg0 = b_gate[lane], bg1 = b_gate[lane + 32];
        float bt0 = b_tau[lane],  bt1 = b_tau[lane + 32];

        for (int p = 0; p < rows_per_warp / 4; p++) {
            int o4 = base + p * 4;
            float tg0[4], tg1[4], h0[4], h1[4];
            #pragma unroll
            for (int j = 0; j < 4; j++) {
                tg0[j] = lora_B[(size_t)(o4 + j) * RR + lane];
                tg1[j] = lora_B[(size_t)(o4 + j) * RR + lane + 32];
                h0[j]  = hidden0[(size_t)(o4 + j) * RR + lane];
                h1[j]  = hidden0[(size_t)(o4 + j) * RR + lane + 32];
            }

            // target-half partial dots, weights streamed from global (L2-hot)
            float pg0[4], pg1[4], pt0[4], pt1[4];
            #pragma unroll
            for (int j = 0; j < 4; j++) { pg0[j] = bg0; pg1[j] = bg1; pt0[j] = bt0; pt1[j] = bt1; }
            #pragma unroll 2
            for (int k0 = 0; k0 < 32; k0 += 4) {
                float4 wg0A = *(const float4*)(W_gate + lane * 128 + k0);
                float4 wg1A = *(const float4*)(W_gate + (lane + 32) * 128 + k0);
                float4 wt0A = *(const float4*)(W_tau  + lane * 128 + k0);
                float4 wt1A = *(const float4*)(W_tau  + (lane + 32) * 128 + k0);
                float4 wg0B = *(const float4*)(W_gate + lane * 128 + 32 + k0);
                float4 wg1B = *(const float4*)(W_gate + (lane + 32) * 128 + 32 + k0);
                float4 wt0B = *(const float4*)(W_tau  + lane * 128 + 32 + k0);
                float4 wt1B = *(const float4*)(W_tau  + (lane + 32) * 128 + 32 + k0);
                #pragma unroll
                for (int e = 0; e < 4; e++) {
                    float g0 = ((const float*)&wg0A)[e], g1 = ((const float*)&wg1A)[e];
                    float t0 = ((const float*)&wt0A)[e], t1 = ((const float*)&wt1A)[e];
                    float g0b = ((const float*)&wg0B)[e], g1b = ((const float*)&wg1B)[e];
                    float t0b = ((const float*)&wt0B)[e], t1b = ((const float*)&wt1B)[e];
                    #pragma unroll
                    for (int j = 0; j < 4; j++) {
                        float v  = __shfl_sync(0xffffffffu, tg0[j], k0 + e);
                        float v2 = __shfl_sync(0xffffffffu, tg1[j], k0 + e);
                        pg0[j] += v * g0;   pg1[j] += v * g1;
                        pt0[j] += v * t0;   pt1[j] += v * t1;
                        pg0[j] += v2 * g0b; pg1[j] += v2 * g1b;
                        pt0[j] += v2 * t0b; pt1[j] += v2 * t1b;
                    }
                }
            }

            #pragma unroll
            for (int step = 0; step < 3; step++) {
                float ga0[4], ga1[4], ta0[4], ta1[4];
                #pragma unroll
                for (int j = 0; j < 4; j++) { ga0[j] = pg0[j]; ga1[j] = pg1[j]; ta0[j] = pt0[j]; ta1[j] = pt1[j]; }
                #pragma unroll 8
                for (int k = 0; k < 32; k++) {
                    float wg0 = WT2[k * 132 + lane],      wg1 = WT2[k * 132 + lane + 32];
                    float wt0 = WT2[k * 132 + 64 + lane], wt1 = WT2[k * 132 + 96 + lane];
                    float wg0b = WT2[(32 + k) * 132 + lane],      wg1b = WT2[(32 + k) * 132 + lane + 32];
                    float wt0b = WT2[(32 + k) * 132 + 64 + lane], wt1b = WT2[(32 + k) * 132 + 96 + lane];
                    #pragma unroll
                    for (int j = 0; j < 4; j++) {
                        float v  = __shfl_sync(0xffffffffu, h0[j], k);
                        float v2 = __shfl_sync(0xffffffffu, h1[j], k);
                        ga0[j] += v * wg0;  ga1[j] += v * wg1;
                        ta0[j] += v * wt0;  ta1[j] += v * wt1;
                        ga0[j] += v2 * wg0b; ga1[j] += v2 * wg1b;
                        ta0[j] += v2 * wt0b; ta1[j] += v2 * wt1b;
                    }
                }
                #pragma unroll
                for (int j = 0; j < 4; j++) {
                    float f0   = 1.0f / (1.0f + expf(-ga0[j]));
                    float f1   = 1.0f / (1.0f + expf(-ga1[j]));
                    float tau0 = TAU_MIN_C + (TAU_MAX_C - TAU_MIN_C) / (1.0f + expf(-ta0[j]));
                    float tau1 = TAU_MIN_C + (TAU_MAX_C - TAU_MIN_C) / (1.0f + expf(-ta1[j]));
                    float a0   = 1.0f / tau0 + f0;
                    float a1   = 1.0f / tau1 + f1;
                    float d0   = expf(-a0 * DT_C);
                    float d1   = expf(-a1 * DT_C);
                    h0[j] = h0[j] * d0 + (f0 / a0) * tg0[j] * (1.0f - d0);
                    h1[j] = h1[j] * d1 + (f1 / a1) * tg1[j] * (1.0f - d1);
                }
            }

            #pragma unroll
            for (int j = 0; j < 4; j++) {
                g_hB[(size_t)(o4 + j) * RR + lane]      = __float2half_rn(SCALING_C * h0[j]);
                g_hB[(size_t)(o4 + j) * RR + lane + 32] = __float2half_rn(SCALING_C * h1[j]);
            }
        }
    }
}

// ---------------------------------------------------------------------------
// Kernel B: out = (th+tl) @ Bh^T   (fp16 2-product, SCALING folded in Bh),
// K = 64 single shot. CTA tile 128(M) x 128(O), 2 CTAs/SM.
// ---------------------------------------------------------------------------
__global__ __launch_bounds__(256, 2) void gemm2_mma(
    float* __restrict__ out, int M, int O)
{
    extern __shared__ char dsm[];
    uint32_t sb  = (smem_u32(dsm) + 1023) & ~1023u;
    uint32_t thi = sb;                 // 128 rows * 128B
    uint32_t tlo = sb + 16384;
    uint32_t bhh = sb + 32768;         // 128 rows * 128B

    int tid = threadIdx.x, wid = tid >> 5, lane = tid & 31;
    int warp_m = wid & 1, warp_n = wid >> 1;
    int tt = lane >> 3, rr = lane & 7;
    int g  = lane >> 2, tq = lane & 3;

    int m0 = blockIdx.x * 128;
    int o0 = blockIdx.y * 128;

    #pragma unroll
    for (int j = 0; j < 4; j++) {
        int i = tid + 256 * j;
        int row = i >> 3, c = i & 7;
        uint4 vh = ((const uint4*)(g_t_hi + (size_t)(m0 + row) * RR))[c];
        uint4 vl = ((const uint4*)(g_t_lo + (size_t)(m0 + row) * RR))[c];
        uint4 vb = ((const uint4*)(g_hB   + (size_t)(o0 + row) * RR))[c];
        uint32_t off = sw128((uint32_t)(row * 128 + c * 16));
        sts128(thi + off, vh.x, vh.y, vh.z, vh.w);
        sts128(tlo + off, vl.x, vl.y, vl.z, vl.w);
        sts128(bhh + off, vb.x, vb.y, vb.z, vb.w);
    }
    __syncthreads();

    int a_row  = warp_m * 64 + (tt & 1) * 8 + rr;   // + mt*16 (4 m-frags)
    int a_colb = (tt >> 1) * 16;
    int b_row  = warp_n * 32 + (tt >> 1) * 8 + rr;  // + np*16 (2 -> 4 n-frags)
    int b_colb = (tt & 1) * 16;

    float acc[4][4][4];
    #pragma unroll
    for (int i = 0; i < 4; i++)
        #pragma unroll
        for (int j = 0; j < 4; j++)
            #pragma unroll
            for (int k = 0; k < 4; k++) acc[i][j][k] = 0.0f;

    #pragma unroll
    for (int kk = 0; kk < 4; kk++) {
        uint32_t bh[4][2];
        #pragma unroll
        for (int np = 0; np < 2; np++) {
            uint32_t off = sw128((uint32_t)((b_row + np * 16) * 128 + b_colb + kk * 32));
            uint32_t r4[4];
            ldm_x4(r4, bhh + off);
            bh[2*np][0] = r4[0]; bh[2*np][1] = r4[1];
            bh[2*np+1][0] = r4[2]; bh[2*np+1][1] = r4[3];
        }
        #pragma unroll
        for (int mt = 0; mt < 4; mt++) {
            uint32_t ath[4], atl[4];
            uint32_t off = sw128((uint32_t)((a_row + mt * 16) * 128 + a_colb + kk * 32));
            ldm_x4(ath, thi + off);
            ldm_x4(atl, tlo + off);
            #pragma unroll
            for (int nt = 0; nt < 4; nt++) {
                mma16816(acc[mt][nt], ath, bh[nt]);
                mma16816(acc[mt][nt], atl, bh[nt]);
            }
        }
    }

    #pragma unroll
    for (int mt = 0; mt < 4; mt++) {
        int m = m0 + warp_m * 64 + mt * 16 + g;
        #pragma unroll
        for (int nt = 0; nt < 4; nt++) {
            int o = o0 + warp_n * 32 + nt * 8 + 2 * tq;
            *(float2*)(out + (size_t)m * O + o)       = make_float2(acc[mt][nt][0], acc[mt][nt][1]);
            *(float2*)(out + (size_t)(m + 8) * O + o) = make_float2(acc[mt][nt][2], acc[mt][nt][3]);
        }
    }
}

// ---------------------------------------------------------------------------
extern "C" void kernel_launch(void* const* d_in, const int* in_sizes, int n_in,
                              void* d_out, int out_size)
{
    const float* x       = (const float*)d_in[0];
    const float* lora_A  = (const float*)d_in[1];
    const float* lora_B  = (const float*)d_in[2];
    const float* hidden0 = (const float*)d_in[3];
    const float* W_gate  = (const float*)d_in[4];
    const float* b_gate  = (const float*)d_in[5];
    const float* W_tau   = (const float*)d_in[6];
    const float* b_tau   = (const float*)d_in[7];
    float* out = (float*)d_out;

    int R = in_sizes[5];                 // 64
    int D = in_sizes[1] / R;             // 4096
    int O = in_sizes[2] / R;             // 4096
    int M = in_sizes[0] / D;             // 16384

    const int smemA = 2 * G1_STAGE + 1024;   // 50176
    const int smemB = 3 * 16384 + 1024;      // 50176

    cudaFuncSetAttribute(fusedA,
                         cudaFuncAttributeMaxDynamicSharedMemorySize, smemA);
    cudaFuncSetAttribute(gemm2_mma,
                         cudaFuncAttributeMaxDynamicSharedMemorySize, smemB);

    int nG1 = M / 64;                    // 256
    fusedA<<<nG1 + NLIQ, 256, smemA>>>(x, lora_A, lora_B, hidden0,
                                       W_gate, b_gate, W_tau, b_tau,
                                       M, D, O, nG1);

    dim3 g2(M / 128, O / 128);
    gemm2_mma<<<g2, 256, smemB>>>(out, M, O);
}